// round 1
// baseline (speedup 1.0000x reference)
#include <cuda_runtime.h>

#define NB     2
#define NN     8192
#define KNN    20
#define COUT   64
#define NCLASS 40
#define BN_EPS 1e-5f

// Scratch (no allocations allowed in kernel_launch)
__device__ float g_sorted[NB][NN];
__device__ float g_dmax[NB][NN];
__device__ float g_dmin[NB][NN];
__device__ float g_x1[NB][COUT];
__device__ float g_x2[NB][COUT];

// ---------------------------------------------------------------------------
// Kernel 1: bitonic sort of each batch's 8192 values, fully in shared memory.
// One block per batch, 1024 threads, 8 elements/thread/substage.
// ---------------------------------------------------------------------------
__global__ void __launch_bounds__(1024, 1) sort_kernel(const float* __restrict__ x) {
    __shared__ float s[NN];
    const int b = blockIdx.x;
    const float* xb = x + b * NN;
    for (int i = threadIdx.x; i < NN; i += 1024) s[i] = xb[i];
    __syncthreads();

    for (int k = 2; k <= NN; k <<= 1) {
        for (int j = k >> 1; j > 0; j >>= 1) {
            #pragma unroll
            for (int r = 0; r < NN / 1024; r++) {
                int t = threadIdx.x + r * 1024;
                int ixj = t ^ j;
                if (ixj > t) {
                    float a = s[t], c = s[ixj];
                    bool up = ((t & k) == 0);
                    if ((a > c) == up) { s[t] = c; s[ixj] = a; }
                }
            }
            __syncthreads();
        }
    }
    for (int i = threadIdx.x; i < NN; i += 1024) g_sorted[b][i] = s[i];
}

// ---------------------------------------------------------------------------
// Kernel 2: for each sorted position p, greedily expand a K-window to the
// K nearest values; record window endpoint deltas (dmin <= 0 <= dmax).
// ---------------------------------------------------------------------------
__global__ void window_kernel() {
    const int p = blockIdx.x * blockDim.x + threadIdx.x;
    const int b = blockIdx.y;
    if (p >= NN) return;
    const float* __restrict__ s = g_sorted[b];
    const float xv = s[p];
    int lo = p, hi = p;
    #pragma unroll
    for (int it = 1; it < KNN; it++) {
        float dl = (lo > 0)      ? (xv - __ldg(&s[lo - 1])) : 3.4e38f;
        float dr = (hi < NN - 1) ? (__ldg(&s[hi + 1]) - xv) : 3.4e38f;
        if (dl <= dr) lo--; else hi++;
    }
    g_dmax[b][p] = s[hi] - xv;
    g_dmin[b][p] = s[lo] - xv;
}

// ---------------------------------------------------------------------------
// Kernel 3: one warp per (batch, out-channel). For each point:
//   h = relu(scale*(w1*x + extreme_k(w0*d)) + shift), then max & mean over N.
// (max_k commutes through the monotone ReLU/affine; sign of scale selects
//  max vs min of w0*d.)
// ---------------------------------------------------------------------------
__global__ void reduce_kernel(const float* __restrict__ conv_w,
                              const float* __restrict__ gamma,
                              const float* __restrict__ beta,
                              const float* __restrict__ mean,
                              const float* __restrict__ var) {
    const int warp = (blockIdx.x * blockDim.x + threadIdx.x) >> 5;
    const int lane = threadIdx.x & 31;
    const int b = warp >> 6;
    const int o = warp & 63;
    if (b >= NB) return;

    const float w0 = conv_w[o * 2 + 0];
    const float w1 = conv_w[o * 2 + 1];
    const float sc = gamma[o] * rsqrtf(var[o] + BN_EPS);
    const float sh = beta[o] - mean[o] * sc;
    const bool pos = (sc >= 0.f);

    float mx = 0.f;   // ReLU output is >= 0
    float sum = 0.f;
    for (int p = lane; p < NN; p += 32) {
        float xv  = g_sorted[b][p];
        float dmx = g_dmax[b][p];
        float dmn = g_dmin[b][p];
        float e = pos ? fmaxf(w0 * dmx, w0 * dmn)
                      : fminf(w0 * dmx, w0 * dmn);
        float h = fmaxf(fmaf(sc, fmaf(w1, xv, e), sh), 0.f);
        mx = fmaxf(mx, h);
        sum += h;
    }
    #pragma unroll
    for (int off = 16; off > 0; off >>= 1) {
        mx  = fmaxf(mx, __shfl_xor_sync(0xffffffffu, mx, off));
        sum += __shfl_xor_sync(0xffffffffu, sum, off);
    }
    if (lane == 0) {
        g_x1[b][o] = mx;
        g_x2[b][o] = sum * (1.0f / NN);
    }
}

// ---------------------------------------------------------------------------
// Kernel 4: out[b,c] = sum_o lin_w[c,o]*x1[b,o] + lin_w[c,64+o]*x2[b,o]
// ---------------------------------------------------------------------------
__global__ void fc_kernel(const float* __restrict__ lin_w, float* __restrict__ out) {
    const int i = blockIdx.x * blockDim.x + threadIdx.x;
    if (i >= NB * NCLASS) return;
    const int b = i / NCLASS;
    const int c = i % NCLASS;
    const float* __restrict__ w = lin_w + c * (2 * COUT);
    float acc = 0.f;
    #pragma unroll 8
    for (int o = 0; o < COUT; o++) {
        acc = fmaf(w[o],        g_x1[b][o], acc);
        acc = fmaf(w[COUT + o], g_x2[b][o], acc);
    }
    out[b * NCLASS + c] = acc;
}

// ---------------------------------------------------------------------------
extern "C" void kernel_launch(void* const* d_in, const int* in_sizes, int n_in,
                              void* d_out, int out_size) {
    const float* x      = (const float*)d_in[0];
    const float* conv_w = (const float*)d_in[1];
    const float* gamma  = (const float*)d_in[2];
    const float* beta   = (const float*)d_in[3];
    const float* mean   = (const float*)d_in[4];
    const float* var    = (const float*)d_in[5];
    const float* lin_w  = (const float*)d_in[6];
    float* out = (float*)d_out;

    sort_kernel<<<NB, 1024>>>(x);

    dim3 g2(NN / 256, NB);
    window_kernel<<<g2, 256>>>();

    // 2 batches * 64 channels = 128 warps = 4096 threads
    reduce_kernel<<<16, 256>>>(conv_w, gamma, beta, mean, var);

    fc_kernel<<<1, 128>>>(lin_w, out);
}

// round 2
// speedup vs baseline: 1.4450x; 1.4450x over previous
#include <cuda_runtime.h>
#include <float.h>

#define NB     2
#define NN     8192
#define KNN    20
#define COUT   64
#define NCLASS 40
#define BN_EPS 1e-5f
#define EPT    8          // elements per thread (NN / 1024)

// Scratch (no allocations allowed)
__device__ float4 g_pack[NB * NN];     // {x, dmin, dmax, 0} per sorted point
__device__ float  g_x1[NB][COUT];
__device__ float  g_x2[NB][COUT];

// ---------------------------------------------------------------------------
// Fused kernel: register/shfl-blocked bitonic sort of 8192 floats + K-window
// expansion. One block per batch, 1024 threads, 8 consecutive elems/thread.
//   j <= 4   : in-register compare-exchange
//   8<=j<=128: __shfl_xor exchange within warp (partner thread = t ^ (j/8))
//   j >= 256 : shared-memory exchange (padded stride 9 -> conflict-free)
// Only 15 of 91 sub-stages touch smem/barriers.
// ---------------------------------------------------------------------------
__global__ void __launch_bounds__(1024, 1) fused_sort_window(const float* __restrict__ x) {
    __shared__ float s[1024 * 9];          // padded exchange buffer (36KB)
    const int t = threadIdx.x;
    const int b = blockIdx.x;

    float v[EPT];
    {
        const float4* xb = (const float4*)(x + b * NN);
        float4 a = xb[t * 2], c = xb[t * 2 + 1];
        v[0] = a.x; v[1] = a.y; v[2] = a.z; v[3] = a.w;
        v[4] = c.x; v[5] = c.y; v[6] = c.z; v[7] = c.w;
    }

    const unsigned FULL = 0xffffffffu;
    for (int k = 2; k <= NN; k <<= 1) {
        for (int j = k >> 1; j > 0; j >>= 1) {
            if (j >= 256) {
                // cross-warp: smem exchange, padded stride 9
                #pragma unroll
                for (int m = 0; m < EPT; m++) s[t * 9 + m] = v[m];
                __syncthreads();
                const int  pt    = t ^ (j >> 3);
                const bool lowup = (((t & (j >> 3)) == 0) == (((t * EPT) & k) == 0));
                #pragma unroll
                for (int m = 0; m < EPT; m++) {
                    float pv = s[pt * 9 + m];
                    v[m] = lowup ? fminf(v[m], pv) : fmaxf(v[m], pv);
                }
                __syncthreads();
            } else if (j >= 8) {
                // intra-warp: shfl exchange
                const int  xm    = j >> 3;
                const bool lowup = (((t & xm) == 0) == (((t * EPT) & k) == 0));
                #pragma unroll
                for (int m = 0; m < EPT; m++) {
                    float pv = __shfl_xor_sync(FULL, v[m], xm);
                    v[m] = lowup ? fminf(v[m], pv) : fmaxf(v[m], pv);
                }
            } else {
                // in-register
                #pragma unroll
                for (int m = 0; m < EPT; m++) {
                    if ((m & j) == 0) {
                        bool up = (((t * EPT + m) & k) == 0);
                        float a = v[m], c = v[m ^ j];
                        float mn = fminf(a, c), mx = fmaxf(a, c);
                        v[m]     = up ? mn : mx;
                        v[m ^ j] = up ? mx : mn;
                    }
                }
            }
        }
    }

    // Store sorted values in natural layout for neighbor access
    {
        float4* sn = (float4*)s;
        float4 a = make_float4(v[0], v[1], v[2], v[3]);
        float4 c = make_float4(v[4], v[5], v[6], v[7]);
        sn[t * 2] = a; sn[t * 2 + 1] = c;
    }
    __syncthreads();

    // K-window greedy expansion, 8 interleaved chains for ILP,
    // incremental dl/dr (only the moved side is re-read).
    int   lo[EPT], hi[EPT];
    float dl[EPT], dr[EPT];
    #pragma unroll
    for (int m = 0; m < EPT; m++) {
        int p = t * EPT + m;
        lo[m] = p; hi[m] = p;
        dl[m] = (p > 0)      ? (v[m] - s[p - 1]) : FLT_MAX;
        dr[m] = (p < NN - 1) ? (s[p + 1] - v[m]) : FLT_MAX;
    }
    for (int it = 1; it < KNN; it++) {
        #pragma unroll
        for (int m = 0; m < EPT; m++) {
            if (dl[m] <= dr[m]) {
                lo[m]--;
                dl[m] = (lo[m] > 0) ? (v[m] - s[lo[m] - 1]) : FLT_MAX;
            } else {
                hi[m]++;
                dr[m] = (hi[m] < NN - 1) ? (s[hi[m] + 1] - v[m]) : FLT_MAX;
            }
        }
    }

    float4* gp = g_pack + b * NN;
    #pragma unroll
    for (int m = 0; m < EPT; m++) {
        int p = t * EPT + m;
        gp[p] = make_float4(v[m], s[lo[m]] - v[m], s[hi[m]] - v[m], 0.f);
    }
}

// ---------------------------------------------------------------------------
// Reduce: one block per (batch, channel). 256 threads scan 8192 packed points
// (one LDG.128 each), warp + smem tree reduce for max & sum.
// ---------------------------------------------------------------------------
__global__ void __launch_bounds__(256) reduce_kernel(const float* __restrict__ conv_w,
                                                     const float* __restrict__ gamma,
                                                     const float* __restrict__ beta,
                                                     const float* __restrict__ mean,
                                                     const float* __restrict__ var) {
    __shared__ float smx[8], ssm[8];
    const int b = blockIdx.x >> 6;
    const int o = blockIdx.x & 63;

    const float w0 = conv_w[o * 2 + 0];
    const float w1 = conv_w[o * 2 + 1];
    const float sc = gamma[o] * rsqrtf(var[o] + BN_EPS);
    const float sh = beta[o] - mean[o] * sc;
    const bool pos = (sc >= 0.f);

    const float4* __restrict__ gp = g_pack + b * NN;
    float mx = 0.f, sum = 0.f;
    #pragma unroll 4
    for (int p = threadIdx.x; p < NN; p += 256) {
        float4 q = gp[p];
        float e = pos ? fmaxf(w0 * q.y, w0 * q.z)
                      : fminf(w0 * q.y, w0 * q.z);
        float h = fmaxf(fmaf(sc, fmaf(w1, q.x, e), sh), 0.f);
        mx = fmaxf(mx, h);
        sum += h;
    }
    #pragma unroll
    for (int off = 16; off > 0; off >>= 1) {
        mx  = fmaxf(mx, __shfl_xor_sync(0xffffffffu, mx, off));
        sum += __shfl_xor_sync(0xffffffffu, sum, off);
    }
    const int warp = threadIdx.x >> 5, lane = threadIdx.x & 31;
    if (lane == 0) { smx[warp] = mx; ssm[warp] = sum; }
    __syncthreads();
    if (threadIdx.x == 0) {
        float fmx = smx[0], fsm = ssm[0];
        #pragma unroll
        for (int w = 1; w < 8; w++) { fmx = fmaxf(fmx, smx[w]); fsm += ssm[w]; }
        g_x1[b][o] = fmx;
        g_x2[b][o] = fsm * (1.0f / NN);
    }
}

// ---------------------------------------------------------------------------
// FC: one warp per (batch, class); 128-long dot via 4 FMAs/lane + shfl reduce.
// ---------------------------------------------------------------------------
__global__ void fc_kernel(const float* __restrict__ lin_w, float* __restrict__ out) {
    const int b = blockIdx.x / NCLASS;
    const int c = blockIdx.x % NCLASS;
    const int lane = threadIdx.x;
    const float* __restrict__ w = lin_w + c * (2 * COUT);
    float acc = 0.f;
    #pragma unroll
    for (int i = 0; i < 4; i++) {
        int idx = lane + i * 32;
        float val = (idx < COUT) ? g_x1[b][idx] : g_x2[b][idx - COUT];
        acc = fmaf(w[idx], val, acc);
    }
    #pragma unroll
    for (int off = 16; off > 0; off >>= 1)
        acc += __shfl_xor_sync(0xffffffffu, acc, off);
    if (lane == 0) out[b * NCLASS + c] = acc;
}

// ---------------------------------------------------------------------------
extern "C" void kernel_launch(void* const* d_in, const int* in_sizes, int n_in,
                              void* d_out, int out_size) {
    const float* x      = (const float*)d_in[0];
    const float* conv_w = (const float*)d_in[1];
    const float* gamma  = (const float*)d_in[2];
    const float* beta   = (const float*)d_in[3];
    const float* mean   = (const float*)d_in[4];
    const float* var    = (const float*)d_in[5];
    const float* lin_w  = (const float*)d_in[6];
    float* out = (float*)d_out;

    fused_sort_window<<<NB, 1024>>>(x);
    reduce_kernel<<<NB * COUT, 256>>>(conv_w, gamma, beta, mean, var);
    fc_kernel<<<NB * NCLASS, 32>>>(lin_w, out);
}

// round 3
// speedup vs baseline: 2.0960x; 1.4505x over previous
#include <cuda_runtime.h>
#include <float.h>

#define NB     2
#define NN     8192
#define KNN    20
#define COUT   64
#define NCLASS 40
#define BN_EPS 1e-5f
#define EPT    8

// Scratch (no allocations allowed)
__device__ float4 g_pack[NB * NN];     // {x, dmin, dmax, 0} per sorted point
__device__ float  g_x1[NB][COUT];
__device__ float  g_x2[NB][COUT];

// ---------------------------------------------------------------------------
// Compare-exchange helpers — ALL register indices compile-time constant.
// ---------------------------------------------------------------------------
__device__ __forceinline__ void ce(float& a, float& b, bool up) {
    float mn = fminf(a, b), mx = fmaxf(a, b);
    a = up ? mn : mx;
    b = up ? mx : mn;
}

// In-thread bitonic merge, j = 4,2,1, single direction d.
__device__ __forceinline__ void reg_merge(float v[EPT], bool d) {
    ce(v[0], v[4], d); ce(v[1], v[5], d); ce(v[2], v[6], d); ce(v[3], v[7], d);
    ce(v[0], v[2], d); ce(v[1], v[3], d); ce(v[4], v[6], d); ce(v[5], v[7], d);
    ce(v[0], v[1], d); ce(v[2], v[3], d); ce(v[4], v[5], d); ce(v[6], v[7], d);
}

// In-thread bitonic sort of 8 elements; final run direction d8.
__device__ __forceinline__ void sort8(float v[EPT], bool d8) {
    // k=2 : asc, desc, asc, desc (independent of t)
    ce(v[0], v[1], true);  ce(v[2], v[3], false);
    ce(v[4], v[5], true);  ce(v[6], v[7], false);
    // k=4 : first half asc, second half desc
    ce(v[0], v[2], true);  ce(v[1], v[3], true);
    ce(v[4], v[6], false); ce(v[5], v[7], false);
    ce(v[0], v[1], true);  ce(v[2], v[3], true);
    ce(v[4], v[5], false); ce(v[6], v[7], false);
    // k=8 : full merge in direction d8
    reg_merge(v, d8);
}

// Intra-warp bitonic merge: shfl substages xm_start..1, then reg_merge.
// Constant v indices; xm is a runtime shfl operand (legal & cheap).
__device__ __forceinline__ void warp_merge(float v[EPT], bool d, int xm_start, int t) {
    for (int xm = xm_start; xm >= 1; xm >>= 1) {
        bool lowup = (((t & xm) == 0) == d);
        #pragma unroll
        for (int m = 0; m < EPT; m++) {
            float pv = __shfl_xor_sync(0xffffffffu, v[m], xm);
            v[m] = lowup ? fminf(v[m], pv) : fmaxf(v[m], pv);
        }
    }
    reg_merge(v, d);
}

// ---------------------------------------------------------------------------
// Fused sort (register/shfl/smem-blocked bitonic) + K-window expansion.
// One block per batch, 1024 threads, 8 consecutive elements per thread.
// ---------------------------------------------------------------------------
__global__ void __launch_bounds__(1024, 1) fused_sort_window(const float* __restrict__ x) {
    __shared__ float s[NN];                      // 32KB exchange + neighbor buffer
    float4* sA = (float4*)s;                     // words [0, 4096):   v[0..3] per thread
    float4* sB = (float4*)(s + 4096);            // words [4096,8192): v[4..7] per thread
    const int t = threadIdx.x;
    const int b = blockIdx.x;

    float v[EPT];
    {
        const float4* xb = (const float4*)(x + b * NN);
        float4 a = xb[t * 2], c = xb[t * 2 + 1];
        v[0] = a.x; v[1] = a.y; v[2] = a.z; v[3] = a.w;
        v[4] = c.x; v[5] = c.y; v[6] = c.z; v[7] = c.w;
    }

    // k = 2,4,8 : fully in-thread
    sort8(v, (t & 1) == 0);

    // k = 16..256 : intra-warp merges
    for (int k = 16; k <= 256; k <<= 1)
        warp_merge(v, (t & (k >> 3)) == 0, k >> 4, t);

    // k = 512..8192 : smem substages (j >= 256) then intra-warp tail
    for (int k = 512; k <= NN; k <<= 1) {
        const bool d = ((t & (k >> 3)) == 0);
        for (int j = k >> 1; j >= 256; j >>= 1) {
            sA[t] = make_float4(v[0], v[1], v[2], v[3]);
            sB[t] = make_float4(v[4], v[5], v[6], v[7]);
            __syncthreads();
            const int  pt    = t ^ (j >> 3);
            const bool lowup = (((t & (j >> 3)) == 0) == d);
            float4 pa = sA[pt], pb = sB[pt];
            v[0] = lowup ? fminf(v[0], pa.x) : fmaxf(v[0], pa.x);
            v[1] = lowup ? fminf(v[1], pa.y) : fmaxf(v[1], pa.y);
            v[2] = lowup ? fminf(v[2], pa.z) : fmaxf(v[2], pa.z);
            v[3] = lowup ? fminf(v[3], pa.w) : fmaxf(v[3], pa.w);
            v[4] = lowup ? fminf(v[4], pb.x) : fmaxf(v[4], pb.x);
            v[5] = lowup ? fminf(v[5], pb.y) : fmaxf(v[5], pb.y);
            v[6] = lowup ? fminf(v[6], pb.z) : fmaxf(v[6], pb.z);
            v[7] = lowup ? fminf(v[7], pb.w) : fmaxf(v[7], pb.w);
            __syncthreads();
        }
        warp_merge(v, d, 16, t);
    }

    // Natural layout for neighbor access
    {
        float4* sn = (float4*)s;
        sn[t * 2]     = make_float4(v[0], v[1], v[2], v[3]);
        sn[t * 2 + 1] = make_float4(v[4], v[5], v[6], v[7]);
    }
    __syncthreads();

    // K-window greedy expansion: 8 interleaved chains, incremental dl/dr.
    int   lo[EPT], hi[EPT];
    float dl[EPT], dr[EPT];
    #pragma unroll
    for (int m = 0; m < EPT; m++) {
        int p = t * EPT + m;
        lo[m] = p; hi[m] = p;
        dl[m] = (p > 0)      ? (v[m] - s[p - 1]) : FLT_MAX;
        dr[m] = (p < NN - 1) ? (s[p + 1] - v[m]) : FLT_MAX;
    }
    for (int it = 1; it < KNN; it++) {
        #pragma unroll
        for (int m = 0; m < EPT; m++) {
            if (dl[m] <= dr[m]) {
                lo[m]--;
                dl[m] = (lo[m] > 0) ? (v[m] - s[lo[m] - 1]) : FLT_MAX;
            } else {
                hi[m]++;
                dr[m] = (hi[m] < NN - 1) ? (s[hi[m] + 1] - v[m]) : FLT_MAX;
            }
        }
    }

    float4* gp = g_pack + b * NN;
    #pragma unroll
    for (int m = 0; m < EPT; m++) {
        int p = t * EPT + m;
        gp[p] = make_float4(v[m], s[lo[m]] - v[m], s[hi[m]] - v[m], 0.f);
    }
}

// ---------------------------------------------------------------------------
// Reduce: one block per (batch, channel); max & mean over 8192 points.
// ---------------------------------------------------------------------------
__global__ void __launch_bounds__(256) reduce_kernel(const float* __restrict__ conv_w,
                                                     const float* __restrict__ gamma,
                                                     const float* __restrict__ beta,
                                                     const float* __restrict__ mean,
                                                     const float* __restrict__ var) {
    __shared__ float smx[8], ssm[8];
    const int b = blockIdx.x >> 6;
    const int o = blockIdx.x & 63;

    const float w0 = conv_w[o * 2 + 0];
    const float w1 = conv_w[o * 2 + 1];
    const float sc = gamma[o] * rsqrtf(var[o] + BN_EPS);
    const float sh = beta[o] - mean[o] * sc;
    const bool pos = (sc >= 0.f);

    const float4* __restrict__ gp = g_pack + b * NN;
    float mx = 0.f, sum = 0.f;
    #pragma unroll 4
    for (int p = threadIdx.x; p < NN; p += 256) {
        float4 q = gp[p];
        float e = pos ? fmaxf(w0 * q.y, w0 * q.z)
                      : fminf(w0 * q.y, w0 * q.z);
        float h = fmaxf(fmaf(sc, fmaf(w1, q.x, e), sh), 0.f);
        mx = fmaxf(mx, h);
        sum += h;
    }
    #pragma unroll
    for (int off = 16; off > 0; off >>= 1) {
        mx  = fmaxf(mx, __shfl_xor_sync(0xffffffffu, mx, off));
        sum += __shfl_xor_sync(0xffffffffu, sum, off);
    }
    const int warp = threadIdx.x >> 5, lane = threadIdx.x & 31;
    if (lane == 0) { smx[warp] = mx; ssm[warp] = sum; }
    __syncthreads();
    if (threadIdx.x == 0) {
        float fmx = smx[0], fsm = ssm[0];
        #pragma unroll
        for (int w = 1; w < 8; w++) { fmx = fmaxf(fmx, smx[w]); fsm += ssm[w]; }
        g_x1[b][o] = fmx;
        g_x2[b][o] = fsm * (1.0f / NN);
    }
}

// ---------------------------------------------------------------------------
// FC: one warp per (batch, class).
// ---------------------------------------------------------------------------
__global__ void fc_kernel(const float* __restrict__ lin_w, float* __restrict__ out) {
    const int b = blockIdx.x / NCLASS;
    const int c = blockIdx.x % NCLASS;
    const int lane = threadIdx.x;
    const float* __restrict__ w = lin_w + c * (2 * COUT);
    float acc = 0.f;
    #pragma unroll
    for (int i = 0; i < 4; i++) {
        int idx = lane + i * 32;
        float val = (idx < COUT) ? g_x1[b][idx] : g_x2[b][idx - COUT];
        acc = fmaf(w[idx], val, acc);
    }
    #pragma unroll
    for (int off = 16; off > 0; off >>= 1)
        acc += __shfl_xor_sync(0xffffffffu, acc, off);
    if (lane == 0) out[b * NCLASS + c] = acc;
}

// ---------------------------------------------------------------------------
extern "C" void kernel_launch(void* const* d_in, const int* in_sizes, int n_in,
                              void* d_out, int out_size) {
    const float* x      = (const float*)d_in[0];
    const float* conv_w = (const float*)d_in[1];
    const float* gamma  = (const float*)d_in[2];
    const float* beta   = (const float*)d_in[3];
    const float* mean   = (const float*)d_in[4];
    const float* var    = (const float*)d_in[5];
    const float* lin_w  = (const float*)d_in[6];
    float* out = (float*)d_out;

    fused_sort_window<<<NB, 1024>>>(x);
    reduce_kernel<<<NB * COUT, 256>>>(conv_w, gamma, beta, mean, var);
    fc_kernel<<<NB * NCLASS, 32>>>(lin_w, out);
}

// round 4
// speedup vs baseline: 4.4035x; 2.1009x over previous
#include <cuda_runtime.h>
#include <float.h>

#define NB     2
#define NN     8192
#define KNN    20
#define COUT   64
#define NCLASS 40
#define BN_EPS 1e-5f
#define EPT    8

// Scratch (no allocations allowed)
__device__ float  g_A[NB * NN];
__device__ float  g_B[NB * NN];
__device__ float4 g_pack[NB * NN];     // {x, dmin, dmax, 0}
__device__ float  g_x1[NB][COUT];
__device__ float  g_x2[NB][COUT];

// ---------------------------------------------------------------------------
// Compare-exchange helpers — ALL register indices compile-time constant.
// Global bitonic rule: at stage k, element i compares ascending iff (i&k)==0.
// ---------------------------------------------------------------------------
__device__ __forceinline__ void ce(float& a, float& b, bool up) {
    float mn = fminf(a, b), mx = fmaxf(a, b);
    a = up ? mn : mx;
    b = up ? mx : mn;
}

__device__ __forceinline__ void reg_merge(float v[EPT], bool d) {
    ce(v[0], v[4], d); ce(v[1], v[5], d); ce(v[2], v[6], d); ce(v[3], v[7], d);
    ce(v[0], v[2], d); ce(v[1], v[3], d); ce(v[4], v[6], d); ce(v[5], v[7], d);
    ce(v[0], v[1], d); ce(v[2], v[3], d); ce(v[4], v[5], d); ce(v[6], v[7], d);
}

__device__ __forceinline__ void sort8(float v[EPT], bool d8) {
    ce(v[0], v[1], true);  ce(v[2], v[3], false);
    ce(v[4], v[5], true);  ce(v[6], v[7], false);
    ce(v[0], v[2], true);  ce(v[1], v[3], true);
    ce(v[4], v[6], false); ce(v[5], v[7], false);
    ce(v[0], v[1], true);  ce(v[2], v[3], true);
    ce(v[4], v[5], false); ce(v[6], v[7], false);
    reg_merge(v, d8);
}

__device__ __forceinline__ void warp_merge(float v[EPT], bool d, int xm_start, int t) {
    for (int xm = xm_start; xm >= 1; xm >>= 1) {
        bool lowup = (((t & xm) == 0) == d);
        #pragma unroll
        for (int m = 0; m < EPT; m++) {
            float pv = __shfl_xor_sync(0xffffffffu, v[m], xm);
            v[m] = lowup ? fminf(v[m], pv) : fmaxf(v[m], pv);
        }
    }
    reg_merge(v, d);
}

// smem substages j = jstart..256, then intra-warp tail (j<=128).
template<int T>
__device__ __forceinline__ void block_merge(float v[EPT], float4* sA, int t,
                                            bool d, int jstart) {
    float4* sB = sA + T;
    for (int j = jstart; j >= 256; j >>= 1) {
        sA[t] = make_float4(v[0], v[1], v[2], v[3]);
        sB[t] = make_float4(v[4], v[5], v[6], v[7]);
        __syncthreads();
        const int  pt    = t ^ (j >> 3);
        const bool lowup = (((t & (j >> 3)) == 0) == d);
        float4 pa = sA[pt], pb = sB[pt];
        v[0] = lowup ? fminf(v[0], pa.x) : fmaxf(v[0], pa.x);
        v[1] = lowup ? fminf(v[1], pa.y) : fmaxf(v[1], pa.y);
        v[2] = lowup ? fminf(v[2], pa.z) : fmaxf(v[2], pa.z);
        v[3] = lowup ? fminf(v[3], pa.w) : fmaxf(v[3], pa.w);
        v[4] = lowup ? fminf(v[4], pb.x) : fmaxf(v[4], pb.x);
        v[5] = lowup ? fminf(v[5], pb.y) : fmaxf(v[5], pb.y);
        v[6] = lowup ? fminf(v[6], pb.z) : fmaxf(v[6], pb.z);
        v[7] = lowup ? fminf(v[7], pb.w) : fmaxf(v[7], pb.w);
        __syncthreads();
    }
    warp_merge(v, d, 16, t);
}

// ---------------------------------------------------------------------------
// L1: sort each 1024-chunk (k = 2..1024). 16 blocks x 128 threads. x -> g_A.
// ---------------------------------------------------------------------------
__global__ void __launch_bounds__(128, 1) k_sort1024(const float* __restrict__ x) {
    __shared__ float4 s[256];              // 1024 floats
    const int t = threadIdx.x;
    const int b = blockIdx.y, cx = blockIdx.x;
    const float4* src = (const float4*)(x + b * NN + cx * 1024);

    float v[EPT];
    { float4 a = src[t * 2], c = src[t * 2 + 1];
      v[0]=a.x; v[1]=a.y; v[2]=a.z; v[3]=a.w;
      v[4]=c.x; v[5]=c.y; v[6]=c.z; v[7]=c.w; }

    sort8(v, (t & 1) == 0);                           // k = 2,4,8
    for (int k = 16; k <= 256; k <<= 1)               // k = 16..256
        warp_merge(v, (t & (k >> 3)) == 0, k >> 4, t);
    block_merge<128>(v, s, t, (t & 64) == 0, 256);    // k = 512
    block_merge<128>(v, s, t, (cx & 1) == 0, 512);    // k = 1024

    float4* dst = (float4*)(g_A + b * NN + cx * 1024);
    dst[t * 2]     = make_float4(v[0], v[1], v[2], v[3]);
    dst[t * 2 + 1] = make_float4(v[4], v[5], v[6], v[7]);
}

// ---------------------------------------------------------------------------
// L2: stages k=2048, k=4096 — block-local on 4096-chunks. 4 blocks x 512 thr.
// ---------------------------------------------------------------------------
__global__ void __launch_bounds__(512, 1) k_merge4096() {
    __shared__ float4 s[1024];             // 4096 floats (16KB)
    const int t = threadIdx.x;
    const int b = blockIdx.y, cx = blockIdx.x;
    float4* buf = (float4*)(g_A + b * NN + cx * 4096);

    float v[EPT];
    { float4 a = buf[t * 2], c = buf[t * 2 + 1];
      v[0]=a.x; v[1]=a.y; v[2]=a.z; v[3]=a.w;
      v[4]=c.x; v[5]=c.y; v[6]=c.z; v[7]=c.w; }

    block_merge<512>(v, s, t, (t & 256) == 0, 1024);  // k = 2048
    block_merge<512>(v, s, t, (cx & 1) == 0, 2048);   // k = 4096

    buf[t * 2]     = make_float4(v[0], v[1], v[2], v[3]);
    buf[t * 2 + 1] = make_float4(v[4], v[5], v[6], v[7]);
}

// ---------------------------------------------------------------------------
// L3: k=8192, j=4096 cross-chunk compare-exchange. g_A -> g_B (ping-pong).
// 16 blocks x 256 threads, one float4 each. Ascending (final stage).
// ---------------------------------------------------------------------------
__global__ void __launch_bounds__(256) k_cross4096() {
    const int b = blockIdx.y, cx = blockIdx.x, tid = threadIdx.x;
    const float4* s4 = (const float4*)(g_A + b * NN);
    float4*       d4 = (float4*)(g_B + b * NN);
    const int q = cx * 256 + tid;
    float4 a = s4[q], p = s4[q ^ 1024];
    float4 r;
    if (cx & 4) {   // (i & 4096) set -> keep max
        r.x = fmaxf(a.x, p.x); r.y = fmaxf(a.y, p.y);
        r.z = fmaxf(a.z, p.z); r.w = fmaxf(a.w, p.w);
    } else {        // keep min
        r.x = fminf(a.x, p.x); r.y = fminf(a.y, p.y);
        r.z = fminf(a.z, p.z); r.w = fminf(a.w, p.w);
    }
    d4[q] = r;
}

// ---------------------------------------------------------------------------
// L4: k=8192, j=2048..1 block-local on 4096-chunks (ascending). g_B in-place.
// ---------------------------------------------------------------------------
__global__ void __launch_bounds__(512, 1) k_final4096() {
    __shared__ float4 s[1024];
    const int t = threadIdx.x;
    const int b = blockIdx.y, cx = blockIdx.x;
    float4* buf = (float4*)(g_B + b * NN + cx * 4096);

    float v[EPT];
    { float4 a = buf[t * 2], c = buf[t * 2 + 1];
      v[0]=a.x; v[1]=a.y; v[2]=a.z; v[3]=a.w;
      v[4]=c.x; v[5]=c.y; v[6]=c.z; v[7]=c.w; }

    block_merge<512>(v, s, t, true, 2048);

    buf[t * 2]     = make_float4(v[0], v[1], v[2], v[3]);
    buf[t * 2 + 1] = make_float4(v[4], v[5], v[6], v[7]);
}

// ---------------------------------------------------------------------------
// Window: K-nearest window per point on the sorted array (smem halo +-19).
// grid (32, NB) x 256 threads, one point per thread.
// ---------------------------------------------------------------------------
__global__ void __launch_bounds__(256) k_window() {
    __shared__ float sw[256 + 2 * (KNN - 1) + 2];
    const int b = blockIdx.y;
    const int p0 = blockIdx.x * 256;
    const float* __restrict__ src = g_B + b * NN;

    for (int i = threadIdx.x; i < 256 + 2 * (KNN - 1); i += 256) {
        int g = p0 - (KNN - 1) + i;
        sw[i] = (g >= 0 && g < NN) ? src[g] : 0.f;   // halo garbage never read
    }
    __syncthreads();

    const int p   = p0 + threadIdx.x;
    const int off = (KNN - 1) - p0;                  // global -> smem index
    const float xv = sw[p + off];
    int lo = p, hi = p;
    float dl = (lo > 0)      ? (xv - sw[lo - 1 + off]) : FLT_MAX;
    float dr = (hi < NN - 1) ? (sw[hi + 1 + off] - xv) : FLT_MAX;
    #pragma unroll
    for (int it = 1; it < KNN; it++) {
        if (dl <= dr) {
            lo--;
            dl = (lo > 0) ? (xv - sw[lo - 1 + off]) : FLT_MAX;
        } else {
            hi++;
            dr = (hi < NN - 1) ? (sw[hi + 1 + off] - xv) : FLT_MAX;
        }
    }
    g_pack[b * NN + p] = make_float4(xv, sw[lo + off] - xv, sw[hi + off] - xv, 0.f);
}

// ---------------------------------------------------------------------------
// Reduce: one block per (batch, channel); max & mean over 8192 points.
// ---------------------------------------------------------------------------
__global__ void __launch_bounds__(256) reduce_kernel(const float* __restrict__ conv_w,
                                                     const float* __restrict__ gamma,
                                                     const float* __restrict__ beta,
                                                     const float* __restrict__ mean,
                                                     const float* __restrict__ var) {
    __shared__ float smx[8], ssm[8];
    const int b = blockIdx.x >> 6;
    const int o = blockIdx.x & 63;

    const float w0 = conv_w[o * 2 + 0];
    const float w1 = conv_w[o * 2 + 1];
    const float sc = gamma[o] * rsqrtf(var[o] + BN_EPS);
    const float sh = beta[o] - mean[o] * sc;
    const bool pos = (sc >= 0.f);

    const float4* __restrict__ gp = g_pack + b * NN;
    float mx = 0.f, sum = 0.f;
    #pragma unroll 4
    for (int p = threadIdx.x; p < NN; p += 256) {
        float4 q = gp[p];
        float e = pos ? fmaxf(w0 * q.y, w0 * q.z)
                      : fminf(w0 * q.y, w0 * q.z);
        float h = fmaxf(fmaf(sc, fmaf(w1, q.x, e), sh), 0.f);
        mx = fmaxf(mx, h);
        sum += h;
    }
    #pragma unroll
    for (int off = 16; off > 0; off >>= 1) {
        mx  = fmaxf(mx, __shfl_xor_sync(0xffffffffu, mx, off));
        sum += __shfl_xor_sync(0xffffffffu, sum, off);
    }
    const int warp = threadIdx.x >> 5, lane = threadIdx.x & 31;
    if (lane == 0) { smx[warp] = mx; ssm[warp] = sum; }
    __syncthreads();
    if (threadIdx.x == 0) {
        float fmx = smx[0], fsm = ssm[0];
        #pragma unroll
        for (int w = 1; w < 8; w++) { fmx = fmaxf(fmx, smx[w]); fsm += ssm[w]; }
        g_x1[b][o] = fmx;
        g_x2[b][o] = fsm * (1.0f / NN);
    }
}

// ---------------------------------------------------------------------------
// FC: one warp per (batch, class).
// ---------------------------------------------------------------------------
__global__ void fc_kernel(const float* __restrict__ lin_w, float* __restrict__ out) {
    const int b = blockIdx.x / NCLASS;
    const int c = blockIdx.x % NCLASS;
    const int lane = threadIdx.x;
    const float* __restrict__ w = lin_w + c * (2 * COUT);
    float acc = 0.f;
    #pragma unroll
    for (int i = 0; i < 4; i++) {
        int idx = lane + i * 32;
        float val = (idx < COUT) ? g_x1[b][idx] : g_x2[b][idx - COUT];
        acc = fmaf(w[idx], val, acc);
    }
    #pragma unroll
    for (int off = 16; off > 0; off >>= 1)
        acc += __shfl_xor_sync(0xffffffffu, acc, off);
    if (lane == 0) out[b * NCLASS + c] = acc;
}

// ---------------------------------------------------------------------------
extern "C" void kernel_launch(void* const* d_in, const int* in_sizes, int n_in,
                              void* d_out, int out_size) {
    const float* x      = (const float*)d_in[0];
    const float* conv_w = (const float*)d_in[1];
    const float* gamma  = (const float*)d_in[2];
    const float* beta   = (const float*)d_in[3];
    const float* mean   = (const float*)d_in[4];
    const float* var    = (const float*)d_in[5];
    const float* lin_w  = (const float*)d_in[6];
    float* out = (float*)d_out;

    k_sort1024<<<dim3(8, NB), 128>>>(x);       // k <= 1024
    k_merge4096<<<dim3(2, NB), 512>>>();       // k = 2048, 4096
    k_cross4096<<<dim3(8, NB), 256>>>();       // k = 8192, j = 4096
    k_final4096<<<dim3(2, NB), 512>>>();       // k = 8192, j <= 2048
    k_window<<<dim3(32, NB), 256>>>();
    reduce_kernel<<<NB * COUT, 256>>>(conv_w, gamma, beta, mean, var);
    fc_kernel<<<NB * NCLASS, 32>>>(lin_w, out);
}